// round 17
// baseline (speedup 1.0000x reference)
#include <cuda_runtime.h>
#include <cuda_bf16.h>
#include <cuda_fp16.h>
#include <math.h>
#include <stdint.h>

namespace {

constexpr int B_ = 32;
constexpr int N_ = 64;
constexpr int C_ = 128;
constexpr int M_ = 15;
constexpr int E_ = B_ * N_ * N_;   // 131072
constexpr float LN_EPS = 1e-5f;
constexpr int TSTR = 136;          // padded 16-bit row stride (272B: conflict-free ldmatrix)
constexpr int WSEG = 128 * TSTR;   // elements per weight segment

// ---------------- device scratch --------------------------------------------
__device__ __align__(16) __half g_tf16[(size_t)E_ * C_];   // post-LN t, fp16
__device__ __align__(16) float g_row [B_ * N_ * C_];
__device__ __align__(16) float g_col [B_ * N_ * C_];
__device__ __align__(16) float g_diag[B_ * N_ * C_];
__device__ __align__(16) float g_A [B_ * N_ * C_];
__device__ __align__(16) float g_Bv[B_ * N_ * C_];
__device__ __align__(16) float g_D [B_ * N_ * C_];
__device__ __align__(16) float g_Cc[B_ * C_];
__device__ __align__(16) float g_Ec[B_ * C_];
__device__ __align__(16) float g_WT[M_ * C_ * C_];        // [m][c][o]
__device__ __align__(16) __half g_Wf[2 * WSEG];           // {W0 f16, W1 f16}

// ---------------- helpers ----------------------------------------------------
__device__ __forceinline__ float gelu_exact(float v) {
    return 0.5f * v * (1.0f + erff(v * 0.70710678118654752440f));
}
__device__ __forceinline__ uint32_t smem_to_u32(const void* p) {
    uint32_t a;
    asm("{ .reg .u64 t; cvta.to.shared.u64 t, %1; cvt.u32.u64 %0, t; }" : "=r"(a) : "l"(p));
    return a;
}
__device__ __forceinline__ void ldsm4(uint32_t* r, uint32_t addr) {
    asm volatile("ldmatrix.sync.aligned.m8n8.x4.shared.b16 {%0,%1,%2,%3}, [%4];"
                 : "=r"(r[0]), "=r"(r[1]), "=r"(r[2]), "=r"(r[3]) : "r"(addr));
}
__device__ __forceinline__ void mma_f16(float* d, const uint32_t* a,
                                        uint32_t b0, uint32_t b1) {
    asm volatile("mma.sync.aligned.m16n8k16.row.col.f32.f16.f16.f32 "
                 "{%0,%1,%2,%3}, {%4,%5,%6,%7}, {%8,%9}, {%0,%1,%2,%3};"
                 : "+f"(d[0]), "+f"(d[1]), "+f"(d[2]), "+f"(d[3])
                 : "r"(a[0]), "r"(a[1]), "r"(a[2]), "r"(a[3]), "r"(b0), "r"(b1));
}
__device__ __forceinline__ uint2 cvt_h4(float4 v) {
    __half2 h0 = __floats2half2_rn(v.x, v.y);
    __half2 h1 = __floats2half2_rn(v.z, v.w);
    uint2 r;
    r.x = *reinterpret_cast<uint32_t*>(&h0);
    r.y = *reinterpret_cast<uint32_t*>(&h1);
    return r;
}

#define CP_ASYNC16(dst, src) \
    asm volatile("cp.async.cg.shared.global [%0], [%1], 16;" :: "r"(dst), "l"(src))
#define CP_COMMIT() asm volatile("cp.async.commit_group;" ::: "memory")
#define CP_WAIT0()  asm volatile("cp.async.wait_group 0;" ::: "memory")

// ---------------- K1: fp16 warp-MMA input GEMM, X double-buffered -----------
// smem: W @0 (34816), X0 @34816 (17408), X1 @52224 (17408), params, hr.
constexpr int KI_W  = 0;
constexpr int KI_X0 = 34816;
constexpr int KI_X1 = 52224;
constexpr int KI_BI = 69632;
constexpr int KI_LG = 70144;
constexpr int KI_LB = 70656;
constexpr int KI_HR = 71168;   // halfred[64][2] float2 = 1024
constexpr int KI_SM = 72192;

__global__ void __launch_bounds__(256, 3) k_input(
        const float* __restrict__ x, const float* __restrict__ Wi,
        const float* __restrict__ bi, const float* __restrict__ lg,
        const float* __restrict__ lb) {
    extern __shared__ __align__(16) unsigned char smem[];
    const uint32_t sb = smem_to_u32(smem);
    const int tid = threadIdx.x, wid = tid >> 5, lane = tid & 31;
    const int j0 = (wid & 3) * 16, nh = wid >> 2;
    const int rg = lane >> 2, c2 = (lane & 3) * 2;

    // stage W_in as fp16 (once per block)
    for (int u = 0; u < 16; u++) {
        int idx = u * 256 + tid;
        int o = idx >> 5, c4 = (idx & 31) * 4;
        float4 v = *reinterpret_cast<const float4*>(Wi + o * C_ + c4);
        *reinterpret_cast<uint2*>(smem + KI_W + (uint32_t)(o * TSTR + c4) * 2) = cvt_h4(v);
    }
    if (tid < 128) {
        reinterpret_cast<float*>(smem + KI_BI)[tid] = bi[tid];
        reinterpret_cast<float*>(smem + KI_LG)[tid] = lg[tid];
        reinterpret_cast<float*>(smem + KI_LB)[tid] = lb[tid];
    }

    const uint32_t a_off = (uint32_t)((lane & 15) * TSTR + ((lane >> 4) << 3)) * 2;
    const uint32_t b_off = (uint32_t)((((lane >> 4) << 3) + (lane & 7)) * TSTR
                                      + (((lane >> 3) & 1) << 3)) * 2;
    const float* bi_s = reinterpret_cast<const float*>(smem + KI_BI);
    const float* lg_s = reinterpret_cast<const float*>(smem + KI_LG);
    const float* lb_s = reinterpret_cast<const float*>(smem + KI_LB);
    float2* hr = reinterpret_cast<float2*>(smem + KI_HR);

    auto stageX = [&](int p, int xbase) {
        const float* xs = x + (size_t)p * (N_ * C_);
#pragma unroll 1
        for (int u = 0; u < 8; u++) {
            int idx = u * 256 + tid;
            int r = idx >> 5, c4 = (idx & 31) * 4;
            float4 v = *reinterpret_cast<const float4*>(xs + r * C_ + c4);
            *reinterpret_cast<uint2*>(smem + xbase + (uint32_t)(r * TSTR + c4) * 2) = cvt_h4(v);
        }
    };

    int p = blockIdx.x;
    int cur = 0;
    if (p < B_ * N_) stageX(p, KI_X0);
    __syncthreads();

    for (; p < B_ * N_; p += gridDim.x) {
        const uint32_t xb = sb + (cur ? KI_X1 : KI_X0);

        float acc[8][4];
#pragma unroll
        for (int nt = 0; nt < 8; nt++)
#pragma unroll
            for (int q = 0; q < 4; q++) acc[nt][q] = 0.f;

#pragma unroll 1
        for (int kt = 0; kt < 8; kt++) {
            const uint32_t kb = kt * 32;
            const uint32_t arow = (uint32_t)(j0 * TSTR) * 2 + a_off + kb;
            uint32_t xa[4];
            ldsm4(xa, xb + arow);
#pragma unroll
            for (int np = 0; np < 4; np++) {
                const uint32_t brow =
                    (uint32_t)((nh * 64 + np * 16) * TSTR) * 2 + b_off + kb;
                uint32_t w[4];
                ldsm4(w, sb + KI_W + brow);
#pragma unroll
                for (int e = 0; e < 2; e++) {
                    float* d = acc[np * 2 + e];
                    const int rgi = e * 2;
                    mma_f16(d, xa, w[rgi], w[rgi + 1]);
                }
            }
        }

        // ---- prefetch next tile's X into the other buffer (overlaps epilogue)
        const int pn = p + gridDim.x;
        if (pn < B_ * N_) stageX(pn, cur ? KI_X0 : KI_X1);
        cur ^= 1;

        // ---- epilogue: bias + GELU, LN stats ----
        float sa = 0.f, ssa = 0.f, sbm = 0.f, ssb = 0.f;
#pragma unroll
        for (int nt = 0; nt < 8; nt++) {
            const int o = nh * 64 + nt * 8 + c2;
            const float b0 = bi_s[o], b1 = bi_s[o + 1];
            acc[nt][0] = gelu_exact(acc[nt][0] + b0);
            acc[nt][1] = gelu_exact(acc[nt][1] + b1);
            acc[nt][2] = gelu_exact(acc[nt][2] + b0);
            acc[nt][3] = gelu_exact(acc[nt][3] + b1);
            sa  += acc[nt][0] + acc[nt][1];
            ssa += acc[nt][0] * acc[nt][0] + acc[nt][1] * acc[nt][1];
            sbm += acc[nt][2] + acc[nt][3];
            ssb += acc[nt][2] * acc[nt][2] + acc[nt][3] * acc[nt][3];
        }
#pragma unroll
        for (int off = 1; off <= 2; off <<= 1) {
            sa  += __shfl_xor_sync(0xffffffffu, sa,  off);
            ssa += __shfl_xor_sync(0xffffffffu, ssa, off);
            sbm += __shfl_xor_sync(0xffffffffu, sbm, off);
            ssb += __shfl_xor_sync(0xffffffffu, ssb, off);
        }
        if ((lane & 3) == 0) {
            hr[(j0 + rg) * 2 + nh]     = make_float2(sa, ssa);
            hr[(j0 + rg + 8) * 2 + nh] = make_float2(sbm, ssb);
        }
        __syncthreads();   // also orders prefetch STS before next tile's MMAs
        const int ja = j0 + rg, jb = j0 + rg + 8;
        float2 ha0 = hr[ja * 2 + 0], ha1 = hr[ja * 2 + 1];
        float2 hb0 = hr[jb * 2 + 0], hb1 = hr[jb * 2 + 1];
        const float mua = (ha0.x + ha1.x) * (1.0f / C_);
        const float inva = rsqrtf((ha0.y + ha1.y) * (1.0f / C_) - mua * mua + LN_EPS);
        const float mub = (hb0.x + hb1.x) * (1.0f / C_);
        const float invb = rsqrtf((hb0.y + hb1.y) * (1.0f / C_) - mub * mub + LN_EPS);

        uint32_t* th32 = reinterpret_cast<uint32_t*>(g_tf16);
        const size_t rba = ((size_t)p * N_ + ja) * (C_ / 2);
        const size_t rbb = ((size_t)p * N_ + jb) * (C_ / 2);
#pragma unroll
        for (int nt = 0; nt < 8; nt++) {
            const int o = nh * 64 + nt * 8 + c2;
            const float g0 = lg_s[o], g1 = lg_s[o + 1];
            const float z0 = lb_s[o], z1 = lb_s[o + 1];
            float n0 = (acc[nt][0] - mua) * inva * g0 + z0;
            float n1 = (acc[nt][1] - mua) * inva * g1 + z1;
            float n2 = (acc[nt][2] - mub) * invb * g0 + z0;
            float n3 = (acc[nt][3] - mub) * invb * g1 + z1;
            __half2 h;
            h = __floats2half2_rn(n0, n1);
            th32[rba + (o >> 1)] = *reinterpret_cast<uint32_t*>(&h);
            h = __floats2half2_rn(n2, n3);
            th32[rbb + (o >> 1)] = *reinterpret_cast<uint32_t*>(&h);
        }
        __syncthreads();   // hr safe for reuse before any warp races ahead
    }
}

// ---------------- K2: coeffs + col/diag + row means (unchanged) -------------
__global__ void __launch_bounds__(256) k_colmix(
        const float* __restrict__ c00, const float* __restrict__ c01,
        const float* __restrict__ c10, const float* __restrict__ c11) {
    const int bx = blockIdx.x, tid = threadIdx.x;
    if (bx < 120) {
#pragma unroll
        for (int u = 0; u < 8; u++) {
            int idx = bx * 2048 + u * 256 + tid;
            int o = idx & 127, c = (idx >> 7) & 127, m = idx >> 14;
            float v = c00[o * M_ + m] * c10[o * C_ + c] + c01[c * M_ + m] * c11[o * C_ + c];
            g_WT[idx] = v;
            if (m < 2) g_Wf[m * WSEG + o * TSTR + c] = __float2half_rn(v);
        }
    } else if (bx < 376) {
        const int cb = bx - 120;
        const int b = cb >> 3, qg = cb & 7;
        const int ql = tid >> 5, lane = tid & 31;
        const int q = qg * 8 + ql;
        const int c0 = lane * 4;
        const uint2* th = reinterpret_cast<const uint2*>(g_tf16);
        const size_t base = ((size_t)(b * N_) * N_ + q) * (C_ / 4) + (c0 >> 2);
        const size_t istep = (size_t)N_ * (C_ / 4);
        float s0 = 0.f, s1 = 0.f, s2 = 0.f, s3 = 0.f;
        float d0 = 0.f, d1 = 0.f, d2 = 0.f, d3 = 0.f;
#pragma unroll 4
        for (int i = 0; i < N_; i++) {
            uint2 hv = th[base + (size_t)i * istep];
            __half2 h0 = *reinterpret_cast<__half2*>(&hv.x);
            __half2 h1 = *reinterpret_cast<__half2*>(&hv.y);
            float v0 = __half2float(__low2half(h0));
            float v1 = __half2float(__high2half(h0));
            float v2 = __half2float(__low2half(h1));
            float v3 = __half2float(__high2half(h1));
            s0 += v0; s1 += v1; s2 += v2; s3 += v3;
            if (i == q) { d0 = v0; d1 = v1; d2 = v2; d3 = v3; }
        }
        float* cp = g_col  + (size_t)(b * N_ + q) * C_ + c0;
        float* dp = g_diag + (size_t)(b * N_ + q) * C_ + c0;
        cp[0] = s0 * (1.0f / N_); cp[1] = s1 * (1.0f / N_);
        cp[2] = s2 * (1.0f / N_); cp[3] = s3 * (1.0f / N_);
        dp[0] = d0; dp[1] = d1; dp[2] = d2; dp[3] = d3;
    } else {
        __shared__ float rsum[4][C_];
        const int rb2 = bx - 376;
        const int g = tid >> 6;
        const int cp2 = tid & 63;
#pragma unroll 1
        for (int u = 0; u < 8; u++) {
            const int p = rb2 * 8 + u;
            const uint32_t* tp =
                reinterpret_cast<const uint32_t*>(g_tf16 + (size_t)p * (N_ * C_));
            float s0 = 0.f, s1 = 0.f;
#pragma unroll 4
            for (int jr = 0; jr < 16; jr++) {
                uint32_t hv = tp[(g * 16 + jr) * (C_ / 2) + cp2];
                __half2 h = *reinterpret_cast<__half2*>(&hv);
                s0 += __half2float(__low2half(h));
                s1 += __half2float(__high2half(h));
            }
            rsum[g][cp2 * 2] = s0; rsum[g][cp2 * 2 + 1] = s1;
            __syncthreads();
            if (tid < C_)
                g_row[p * C_ + tid] =
                    (rsum[0][tid] + rsum[1][tid] + rsum[2][tid] + rsum[3][tid]) * (1.0f / N_);
            __syncthreads();
        }
    }
}

// ---------------- K3: A,Bv,D + Cc,Ec (unchanged) ----------------------------
__global__ void __launch_bounds__(512) k_abd_ce() {
    const int tid = threadIdx.x;
    if (blockIdx.x < 128) {
        __shared__ float s_in[3 * 16 * C_];
        float* sd = s_in;
        float* sr = s_in + 16 * C_;
        float* sc = s_in + 32 * C_;
        const int rb = blockIdx.x * 16;
        for (int idx = tid; idx < 16 * C_; idx += 512) {
            sd[idx] = g_diag[rb * C_ + idx];
            sr[idx] = g_row [rb * C_ + idx];
            sc[idx] = g_col [rb * C_ + idx];
        }
        __syncthreads();
        const int o = tid & 127, grp = tid >> 7;
        const float* W[9] = {
            g_WT + 2 * C_ * C_, g_WT + 4 * C_ * C_, g_WT + 6 * C_ * C_,
            g_WT + 3 * C_ * C_, g_WT + 5 * C_ * C_, g_WT + 7 * C_ * C_,
            g_WT + 10 * C_ * C_, g_WT + 11 * C_ * C_, g_WT + 12 * C_ * C_
        };
        float acc[4][3];
#pragma unroll
        for (int r = 0; r < 4; r++) { acc[r][0] = acc[r][1] = acc[r][2] = 0.f; }
#pragma unroll 1
        for (int c0 = 0; c0 < C_; c0 += 4) {
            float w[4][9];
#pragma unroll
            for (int u = 0; u < 4; u++) {
                int wi = (c0 + u) * C_ + o;
#pragma unroll
                for (int m = 0; m < 9; m++) w[u][m] = W[m][wi];
            }
#pragma unroll
            for (int u = 0; u < 4; u++) {
                int c = c0 + u;
#pragma unroll
                for (int r = 0; r < 4; r++) {
                    int rr = grp * 4 + r;
                    float d = sd[rr * C_ + c], ro = sr[rr * C_ + c], co = sc[rr * C_ + c];
                    acc[r][0] = fmaf(w[u][0], d, fmaf(w[u][1], ro, fmaf(w[u][2], co, acc[r][0])));
                    acc[r][1] = fmaf(w[u][3], d, fmaf(w[u][4], ro, fmaf(w[u][5], co, acc[r][1])));
                    acc[r][2] = fmaf(w[u][6], d, fmaf(w[u][7], ro, fmaf(w[u][8], co, acc[r][2])));
                }
            }
        }
#pragma unroll
        for (int r = 0; r < 4; r++) {
            int rr = rb + grp * 4 + r;
            g_A [rr * C_ + o] = acc[r][0];
            g_Bv[rr * C_ + o] = acc[r][1];
            g_D [rr * C_ + o] = acc[r][2];
        }
    } else {
        __shared__ float str[C_], sto[C_], red[8][C_];
        const int b = blockIdx.x - 128;
        if (tid < C_) {
            float st = 0.f, so = 0.f;
#pragma unroll 4
            for (int q = 0; q < N_; q++) {
                st += g_diag[(b * N_ + q) * C_ + tid];
                so += g_row [(b * N_ + q) * C_ + tid];
            }
            str[tid] = st * (1.0f / N_);
            sto[tid] = so * (1.0f / N_);
        }
        __syncthreads();
        const int o = tid & 127, grp = tid >> 7;
        const float* W8  = g_WT + 8  * C_ * C_;
        const float* W9  = g_WT + 9  * C_ * C_;
        const float* W13 = g_WT + 13 * C_ * C_;
        const float* W14 = g_WT + 14 * C_ * C_;
        float a = 0.f, e = 0.f;
        for (int c = grp * 32; c < grp * 32 + 32; c++) {
            int wi = c * C_ + o;
            float tr = str[c], to = sto[c];
            a = fmaf(W8 [wi], tr, fmaf(W9 [wi], to, a));
            e = fmaf(W13[wi], tr, fmaf(W14[wi], to, e));
        }
        red[grp][o] = a; red[4 + grp][o] = e;
        __syncthreads();
        if (tid < C_) {
            g_Cc[b * C_ + tid] = red[0][tid] + red[1][tid] + red[2][tid] + red[3][tid];
            g_Ec[b * C_ + tid] = red[4][tid] + red[5][tid] + red[6][tid] + red[7][tid];
        }
    }
}

// ---------------- K4: fp16 warp-MMA main GEMM — N-split (unchanged) ---------
constexpr int HGRID = 222;
constexpr int SMB_W0 = 0;
constexpr int SMB_W1 = 17408;
constexpr int SMB_T1 = 34816;
constexpr int SMB_T2 = 52224;
constexpr int SM_MAIN = 69632;

__global__ void __launch_bounds__(256) k_main(float* __restrict__ out) {
    extern __shared__ __align__(16) unsigned char smem[];
    const uint32_t sb = smem_to_u32(smem);
    const int tid = threadIdx.x, wid = tid >> 5, lane = tid & 31;
    const int j0 = (wid & 3) * 16;
    const int nh = wid >> 2;
    const int h = (blockIdx.x >= HGRID) ? 1 : 0;
    const int bstart = blockIdx.x - h * HGRID;

    {
        const uint4* s0 = reinterpret_cast<const uint4*>(
            reinterpret_cast<const char*>(g_Wf) + (size_t)h * 17408);
        const uint4* s1 = reinterpret_cast<const uint4*>(
            reinterpret_cast<const char*>(g_Wf) + 34816 + (size_t)h * 17408);
        uint4* d0 = reinterpret_cast<uint4*>(smem + SMB_W0);
        uint4* d1 = reinterpret_cast<uint4*>(smem + SMB_W1);
        for (int i = tid; i < 17408 / 16; i += 256) { d0[i] = s0[i]; d1[i] = s1[i]; }
    }

    const uint32_t a_off = (uint32_t)((lane & 15) * TSTR + ((lane >> 4) << 3)) * 2;
    const uint32_t b_off = (uint32_t)((((lane >> 4) << 3) + (lane & 7)) * TSTR
                                      + (((lane >> 3) & 1) << 3)) * 2;

    auto stage = [&](int p) {
        const int b = p >> 6, i = p & 63;
        const char* s1 = reinterpret_cast<const char*>(g_tf16 + (size_t)p * (N_ * C_));
#pragma unroll
        for (int u = 0; u < 4; u++) {
            int ch = u * 256 + tid;
            int r = ch >> 4, c = ch & 15;
            uint32_t dso = (uint32_t)(r * TSTR + c * 8) * 2;
            CP_ASYNC16(sb + SMB_T1 + dso, s1 + ch * 16);
            const size_t r2 = ((size_t)((b * N_ + r) * N_ + i)) * C_;
            CP_ASYNC16(sb + SMB_T2 + dso, reinterpret_cast<const char*>(g_tf16 + r2) + c * 16);
        }
    };

    int p = bstart;
    if (p < B_ * N_) { stage(p); CP_COMMIT(); }
    CP_WAIT0();
    __syncthreads();

    for (; p < B_ * N_; p += HGRID) {
        const int b = p >> 6, i = p & 63;

        float acc[4][4];
#pragma unroll
        for (int nt = 0; nt < 4; nt++)
#pragma unroll
            for (int q = 0; q < 4; q++) acc[nt][q] = 0.f;

#pragma unroll 1
        for (int kt = 0; kt < 8; kt++) {
            const uint32_t kb = kt * 32;
            const uint32_t arow = (uint32_t)(j0 * TSTR) * 2 + a_off + kb;
            uint32_t a1[4], a2[4];
            ldsm4(a1, sb + SMB_T1 + arow);
            ldsm4(a2, sb + SMB_T2 + arow);
#pragma unroll
            for (int np = 0; np < 2; np++) {
                const uint32_t brow =
                    (uint32_t)((nh * 32 + np * 16) * TSTR) * 2 + b_off + kb;
                uint32_t w0[4], w1[4];
                ldsm4(w0, sb + SMB_W0 + brow);
                ldsm4(w1, sb + SMB_W1 + brow);
#pragma unroll
                for (int e = 0; e < 2; e++) {
                    float* d = acc[np * 2 + e];
                    const int rgi = e * 2;
                    mma_f16(d, a1, w0[rgi], w0[rgi + 1]);
                    mma_f16(d, a2, w1[rgi], w1[rgi + 1]);
                }
            }
        }
        __syncthreads();
        const int pn = p + HGRID;
        if (pn < B_ * N_) { stage(pn); CP_COMMIT(); }

        {
            const int rg = lane >> 2;
            const int c2 = (lane & 3) * 2;
            const int ja = j0 + rg, jb = j0 + rg + 8;
            const int ob = h * 64;
            const float* Ap  = g_A  + (size_t)p * C_ + ob;
            const float* Ccp = g_Cc + (size_t)b * C_ + ob;
            const float* Dp  = g_D  + (size_t)p * C_ + ob;
            const float* Ep  = g_Ec + (size_t)b * C_ + ob;
            const float* Bva = g_Bv + ((size_t)(b * N_ + ja)) * C_ + ob;
            const float* Bvb = g_Bv + ((size_t)(b * N_ + jb)) * C_ + ob;
            float* outa = out + ((size_t)p * N_ + ja) * C_ + ob;
            float* outb = out + ((size_t)p * N_ + jb) * C_ + ob;
            const bool da = (ja == i), db = (jb == i);
#pragma unroll
            for (int nt = 0; nt < 4; nt++) {
                const int o = nh * 32 + nt * 8 + c2;
                float2 av = *reinterpret_cast<const float2*>(Ap + o);
                float2 cv = *reinterpret_cast<const float2*>(Ccp + o);
                const float addx = av.x + cv.x, addy = av.y + cv.y;
                float2 dd, ee;
                if (da || db) {
                    dd = *reinterpret_cast<const float2*>(Dp + o);
                    ee = *reinterpret_cast<const float2*>(Ep + o);
                }
                {
                    float2 bv = *reinterpret_cast<const float2*>(Bva + o);
                    float e0 = acc[nt][0] + addx + bv.x;
                    float e1 = acc[nt][1] + addy + bv.y;
                    if (da) { e0 += dd.x + ee.x; e1 += dd.y + ee.y; }
                    float2 o2; o2.x = gelu_exact(e0); o2.y = gelu_exact(e1);
                    *reinterpret_cast<float2*>(outa + o) = o2;
                }
                {
                    float2 bv = *reinterpret_cast<const float2*>(Bvb + o);
                    float e0 = acc[nt][2] + addx + bv.x;
                    float e1 = acc[nt][3] + addy + bv.y;
                    if (db) { e0 += dd.x + ee.x; e1 += dd.y + ee.y; }
                    float2 o2; o2.x = gelu_exact(e0); o2.y = gelu_exact(e1);
                    *reinterpret_cast<float2*>(outb + o) = o2;
                }
            }
        }
        CP_WAIT0();
        __syncthreads();
    }
}

} // anonymous namespace

// ---------------- launch -----------------------------------------------------
extern "C" void kernel_launch(void* const* d_in, const int* in_sizes, int n_in,
                              void* d_out, int out_size) {
    const float* x   = (const float*)d_in[0];
    const float* Wi  = (const float*)d_in[3];
    const float* bi  = (const float*)d_in[4];
    const float* lg  = (const float*)d_in[5];
    const float* lb  = (const float*)d_in[6];
    const float* c00 = (const float*)d_in[7];
    const float* c01 = (const float*)d_in[8];
    const float* c10 = (const float*)d_in[9];
    const float* c11 = (const float*)d_in[10];
    float* out = (float*)d_out;

    cudaFuncSetAttribute(k_input, cudaFuncAttributeMaxDynamicSharedMemorySize, KI_SM);
    cudaFuncSetAttribute(k_main,  cudaFuncAttributeMaxDynamicSharedMemorySize, SM_MAIN);

    k_input <<<444, 256, KI_SM>>>(x, Wi, bi, lg, lb);   // 3/SM, X double-buffered
    k_colmix<<<632, 256>>>(c00, c01, c10, c11);
    k_abd_ce<<<160, 512>>>();
    k_main  <<<2 * HGRID, 256, SM_MAIN>>>(out);         // unchanged
}